// round 9
// baseline (speedup 1.0000x reference)
#include <cuda_runtime.h>

#define ROWS 1024
#define COLS 1024
#define NN (ROWS * COLS)

#define RHOGW 9810.0f            // RHO_W * GRAV
#define INV_SEC_PER_A (1.0f / 31556926.0f)
#define FLOW_COEFF 0.0405f

#define TS 32                    // output tile
#define KF 8                     // fused iterations per launch
#define VSLOTS 34                // vertical slots: 32 + 2 guards
#define HP 18                    // horizontal slot pitch: 16 + 2 guards

// Scratch (device globals: no allocations allowed)
__device__ float4 g_w4[NN];      // incoming weights: {left, right, up, down}
__device__ float  g_runoff[NN];
__device__ float  g_q[2][NN];

// ---------------- fused prep: phi -> gs -> w4 + runoff, one pass ----------------
#define PT 32
#define PH2 36
#define PH1 34

__global__ __launch_bounds__(256) void k_prep(const float* __restrict__ melt,
                                              const float* __restrict__ bed,
                                              const float* __restrict__ wp,
                                              const float* __restrict__ area,
                                              const int*  __restrict__ status) {
    __shared__ float sphi[PH2 * PH2];
    __shared__ float sgs[PH1 * PH1];
    const int ox = blockIdx.x * PT, oy = blockIdx.y * PT;

    for (int idx = threadIdx.x; idx < PH2 * PH2; idx += 256) {
        int iy = idx / PH2, ix = idx % PH2;
        int gy = oy + iy - 2, gx = ox + ix - 2;
        float p = __int_as_float(0x7f800000);     // +INF sentinel: contributes 0 drop
        if (gx >= 0 && gx < COLS && gy >= 0 && gy < ROWS) {
            int g = gy * COLS + gx;
            p = fmaf(RHOGW, bed[g], wp[g]);
        }
        sphi[idx] = p;
    }
    __syncthreads();

    for (int idx = threadIdx.x; idx < PH1 * PH1; idx += 256) {
        int iy = idx / PH1, ix = idx % PH1;
        int gy = oy + iy - 1, gx = ox + ix - 1;
        float gs = 0.0f;
        if (gx >= 0 && gx < COLS && gy >= 0 && gy < ROWS) {
            int g = gy * COLS + gx;
            if (status[g] == 0) {
                int c = (iy + 1) * PH2 + (ix + 1);
                float p = sphi[c];
                float s = 0.0f;
                s += fmaxf(p - sphi[c - 1], 0.0f);
                s += fmaxf(p - sphi[c + 1], 0.0f);
                s += fmaxf(p - sphi[c - PH2], 0.0f);
                s += fmaxf(p - sphi[c + PH2], 0.0f);
                gs = (s > 0.0f) ? (1.0f / s) : 1.0f;
            }
        }
        sgs[idx] = gs;
    }
    __syncthreads();

    for (int idx = threadIdx.x; idx < PT * PT; idx += 256) {
        int iy = idx / PT, ix = idx % PT;
        int gy = oy + iy, gx = ox + ix;
        int g = gy * COLS + gx;
        int cp = (iy + 2) * PH2 + (ix + 2);
        int cg = (iy + 1) * PH1 + (ix + 1);
        float p = sphi[cp];
        float4 w = make_float4(0.0f, 0.0f, 0.0f, 0.0f);
        if (gx > 0)        w.x = fmaxf(sphi[cp - 1]   - p, 0.0f) * sgs[cg - 1];
        if (gx < COLS - 1) w.y = fmaxf(sphi[cp + 1]   - p, 0.0f) * sgs[cg + 1];
        if (gy > 0)        w.z = fmaxf(sphi[cp - PH2] - p, 0.0f) * sgs[cg - PH1];
        if (gy < ROWS - 1) w.w = fmaxf(sphi[cp + PH2] - p, 0.0f) * sgs[cg + PH1];
        g_w4[g] = w;
        g_runoff[g] = melt[g] * area[g] * INV_SEC_PER_A;
    }
}

// ---------------- fused Jacobi: 8 iters, float4-slot ring exchange ----------------
// 256 threads (16x16), each owns a 3x3 patch of a 48x48 region (32x32 tile,
// halo 8). Weights/runoff/q in registers. Ring exchange via ALIGNED float4
// slots: vertical (rows 0/2 of each patch) in vb[slot][tx], horizontal (edge
// cols) in hL/hR[ty][tx]. Every exchange op is LDS.128/STS.128, 512B/warp
// contiguous -> 4 wavefronts, conflict-free.
template <bool INIT, bool FINAL>
__global__ __launch_bounds__(256, 3)
void k_fused(int qsel,
             const float* __restrict__ conduit,
             float* __restrict__ out) {
    __shared__ __align__(16) float4 vb[2][VSLOTS * 16];  // [slot][tx]
    __shared__ __align__(16) float4 hL[2][16 * HP];      // [ty][tx-slot]: patch col 0
    __shared__ __align__(16) float4 hR[2][16 * HP];      // [ty][tx-slot]: patch col 2

    const int tid = threadIdx.x;
    const int tx = tid & 15, ty = tid >> 4;
    const int px = tx * 3, py = ty * 3;
    const int ox = blockIdx.x * TS - KF;
    const int oy = blockIdx.y * TS - KF;

    const float* __restrict__ qsrc = g_q[qsel];
    float*       __restrict__ qdst = g_q[qsel ^ 1];

    // zero guard slots (never written afterwards)
    const float4 z4 = make_float4(0.0f, 0.0f, 0.0f, 0.0f);
    if (tid < 16) {
#pragma unroll
        for (int b = 0; b < 2; b++) {
            vb[b][0 * 16 + tid]             = z4;   // above region
            vb[b][(VSLOTS - 1) * 16 + tid]  = z4;   // below region
            hL[b][tid * HP + 0]             = z4;   // left of region
            hL[b][tid * HP + 17]            = z4;
            hR[b][tid * HP + 0]             = z4;
            hR[b][tid * HP + 17]            = z4;   // right of region
        }
    }

    float4 w[3][3];
    float  ro[3][3];
    float  q[3][3];
#pragma unroll
    for (int r = 0; r < 3; r++) {
#pragma unroll
        for (int c = 0; c < 3; c++) {
            const int gy = oy + py + r, gx = ox + px + c;
            const bool ok = (gx >= 0) & (gx < COLS) & (gy >= 0) & (gy < ROWS);
            const int g = gy * COLS + gx;
            float4 wv = z4;
            float rv = 0.0f, qv = 0.0f;
            if (ok) {
                wv = g_w4[g];
                rv = g_runoff[g];
                qv = INIT ? rv : qsrc[g];
            }
            w[r][c] = wv; ro[r][c] = rv; q[r][c] = qv;
        }
    }

    // slot indices: vertical slot for own row0 = 2*ty+1, row2 = 2*ty+2;
    // ring above = 2*ty (row2 of ty-1, or guard), below = 2*ty+3.
    const int vT = (2 * ty) * 16 + tx;
    const int v0 = (2 * ty + 1) * 16 + tx;
    const int v2 = (2 * ty + 2) * 16 + tx;
    const int vB = (2 * ty + 3) * 16 + tx;
    const int hOwn = ty * HP + tx + 1;
    const int hLft = ty * HP + tx;        // left neighbor's slot
    const int hRgt = ty * HP + tx + 2;    // right neighbor's slot

    // seed iteration-0 exchange values into buffer 0
    vb[0][v0] = make_float4(q[0][0], q[0][1], q[0][2], 0.0f);
    vb[0][v2] = make_float4(q[2][0], q[2][1], q[2][2], 0.0f);
    hL[0][hOwn] = make_float4(q[0][0], q[1][0], q[2][0], 0.0f);
    hR[0][hOwn] = make_float4(q[0][2], q[1][2], q[2][2], 0.0f);
    __syncthreads();

#pragma unroll
    for (int it = 0; it < KF; it++) {
        const int cur = it & 1, nxt = cur ^ 1;

        // 12-ring, previous-iteration values, all LDS.128
        const float4 t4 = vb[cur][vT];     // cells (py-1, px..px+2)
        const float4 b4 = vb[cur][vB];     // cells (py+3, px..px+2)
        const float4 l4 = hR[cur][hLft];   // cells (py..py+2, px-1)
        const float4 r4 = hL[cur][hRgt];   // cells (py..py+2, px+3)
        const float tq[3] = {t4.x, t4.y, t4.z};
        const float bq[3] = {b4.x, b4.y, b4.z};
        const float lq[3] = {l4.x, l4.y, l4.z};
        const float rq[3] = {r4.x, r4.y, r4.z};

        float n[3][3];
#pragma unroll
        for (int r = 0; r < 3; r++) {
#pragma unroll
            for (int c = 0; c < 3; c++) {
                const float lf = (c == 0) ? lq[r] : q[r][c - 1];
                const float rt = (c == 2) ? rq[r] : q[r][c + 1];
                const float up = (r == 0) ? tq[c] : q[r - 1][c];
                const float dn = (r == 2) ? bq[c] : q[r + 1][c];
                float acc = ro[r][c];
                acc = fmaf(w[r][c].x, lf, acc);
                acc = fmaf(w[r][c].y, rt, acc);
                acc = fmaf(w[r][c].z, up, acc);
                acc = fmaf(w[r][c].w, dn, acc);
                n[r][c] = acc;
            }
        }
#pragma unroll
        for (int r = 0; r < 3; r++)
#pragma unroll
            for (int c = 0; c < 3; c++) q[r][c] = n[r][c];

        if (it != KF - 1) {
            // publish exchange slots for next iteration (4x STS.128)
            vb[nxt][v0] = make_float4(q[0][0], q[0][1], q[0][2], 0.0f);
            vb[nxt][v2] = make_float4(q[2][0], q[2][1], q[2][2], 0.0f);
            hL[nxt][hOwn] = make_float4(q[0][0], q[1][0], q[2][0], 0.0f);
            hR[nxt][hOwn] = make_float4(q[0][2], q[1][2], q[2][2], 0.0f);
            __syncthreads();
        }
    }

    // write central 32x32 from registers
#pragma unroll
    for (int r = 0; r < 3; r++) {
#pragma unroll
        for (int c = 0; c < 3; c++) {
            const int ly = py + r, lx = px + c;
            if (lx >= KF && lx < KF + TS && ly >= KF && ly < KF + TS) {
                const int gy = oy + ly, gx = ox + lx;
                const int g = gy * COLS + gx;
                if (FINAL) {
                    const float cd = conduit[g];
                    const float c125 = cd * sqrtf(sqrtf(cd));   // conduit^1.25
                    const float t = q[r][c] * FLOW_COEFF * c125;
                    const bool core = (gx >= 1) & (gx <= COLS - 2) & (gy >= 1) & (gy <= ROWS - 2);
                    out[g] = core ? (t * t) : 0.0f;
                } else {
                    qdst[g] = q[r][c];
                }
            }
        }
    }
}

extern "C" void kernel_launch(void* const* d_in, const int* in_sizes, int n_in,
                              void* d_out, int out_size) {
    const float* melt    = (const float*)d_in[0];
    const float* bed     = (const float*)d_in[1];
    const float* wp      = (const float*)d_in[2];
    const float* area    = (const float*)d_in[3];
    const float* conduit = (const float*)d_in[4];
    const int*   status  = (const int*)d_in[5];
    float* out = (float*)d_out;

    dim3 pgrid(COLS / PT, ROWS / PT);
    k_prep<<<pgrid, 256>>>(melt, bed, wp, area, status);

    dim3 grid(COLS / TS, ROWS / TS);   // 32 x 32 tiles
    // 4 launches x 8 fused iterations = 32 iterations total
    k_fused<true,  false><<<grid, 256>>>(0, conduit, out);  // runoff -> g_q[1]
    k_fused<false, false><<<grid, 256>>>(1, conduit, out);  // g_q[1] -> g_q[0]
    k_fused<false, false><<<grid, 256>>>(0, conduit, out);  // g_q[0] -> g_q[1]
    k_fused<false, true ><<<grid, 256>>>(1, conduit, out);  // g_q[1] -> out
}

// round 10
// speedup vs baseline: 1.2616x; 1.2616x over previous
#include <cuda_runtime.h>

#define ROWS 1024
#define COLS 1024
#define NN (ROWS * COLS)

#define RHOGW 9810.0f            // RHO_W * GRAV
#define INV_SEC_PER_A (1.0f / 31556926.0f)
#define FLOW_COEFF 0.0405f

#define TS 32                    // output tile
#define KF 8                     // fused iterations per launch
#define RW (TS + 2*KF)           // 48
#define RN (RW * RW)             // 2304
#define SPAD RW                  // smem guard pad (one row each side)

// Scratch (device globals: no allocations allowed)
__device__ float4 g_w4[NN];      // incoming weights: {left, right, up, down}
__device__ float  g_runoff[NN];
__device__ float  g_q[2][NN];

// ---------------- fused prep: phi -> gs -> w4 + runoff, one pass ----------------
#define PT 32
#define PH2 36
#define PH1 34

__global__ __launch_bounds__(256) void k_prep(const float* __restrict__ melt,
                                              const float* __restrict__ bed,
                                              const float* __restrict__ wp,
                                              const float* __restrict__ area,
                                              const int*  __restrict__ status) {
    __shared__ float sphi[PH2 * PH2];
    __shared__ float sgs[PH1 * PH1];
    const int ox = blockIdx.x * PT, oy = blockIdx.y * PT;

    for (int idx = threadIdx.x; idx < PH2 * PH2; idx += 256) {
        int iy = idx / PH2, ix = idx % PH2;
        int gy = oy + iy - 2, gx = ox + ix - 2;
        float p = __int_as_float(0x7f800000);     // +INF sentinel: contributes 0 drop
        if (gx >= 0 && gx < COLS && gy >= 0 && gy < ROWS) {
            int g = gy * COLS + gx;
            p = fmaf(RHOGW, bed[g], wp[g]);
        }
        sphi[idx] = p;
    }
    __syncthreads();

    for (int idx = threadIdx.x; idx < PH1 * PH1; idx += 256) {
        int iy = idx / PH1, ix = idx % PH1;
        int gy = oy + iy - 1, gx = ox + ix - 1;
        float gs = 0.0f;
        if (gx >= 0 && gx < COLS && gy >= 0 && gy < ROWS) {
            int g = gy * COLS + gx;
            if (status[g] == 0) {
                int c = (iy + 1) * PH2 + (ix + 1);
                float p = sphi[c];
                float s = 0.0f;
                s += fmaxf(p - sphi[c - 1], 0.0f);
                s += fmaxf(p - sphi[c + 1], 0.0f);
                s += fmaxf(p - sphi[c - PH2], 0.0f);
                s += fmaxf(p - sphi[c + PH2], 0.0f);
                gs = (s > 0.0f) ? (1.0f / s) : 1.0f;
            }
        }
        sgs[idx] = gs;
    }
    __syncthreads();

    for (int idx = threadIdx.x; idx < PT * PT; idx += 256) {
        int iy = idx / PT, ix = idx % PT;
        int gy = oy + iy, gx = ox + ix;
        int g = gy * COLS + gx;
        int cp = (iy + 2) * PH2 + (ix + 2);
        int cg = (iy + 1) * PH1 + (ix + 1);
        float p = sphi[cp];
        float4 w = make_float4(0.0f, 0.0f, 0.0f, 0.0f);
        if (gx > 0)        w.x = fmaxf(sphi[cp - 1]   - p, 0.0f) * sgs[cg - 1];
        if (gx < COLS - 1) w.y = fmaxf(sphi[cp + 1]   - p, 0.0f) * sgs[cg + 1];
        if (gy > 0)        w.z = fmaxf(sphi[cp - PH2] - p, 0.0f) * sgs[cg - PH1];
        if (gy < ROWS - 1) w.w = fmaxf(sphi[cp + PH2] - p, 0.0f) * sgs[cg + PH1];
        g_w4[g] = w;
        g_runoff[g] = melt[g] * area[g] * INV_SEC_PER_A;
    }
}

// ---------------- fused Jacobi: 8 iters, 3x3 patch in registers (R2 scheme) ----------------
// 256 threads (16x16), each owns a 3x3 patch of a 48x48 region (32x32 tile,
// halo 8). Interior neighbor values live in registers; only the 12-ring is read
// from smem and only the 8 border cells are written per iteration. The last
// iteration publishes nothing (values exit via registers).
template <bool INIT, bool FINAL>
__global__ __launch_bounds__(256, 3)
void k_fused(int qsel,
             const float* __restrict__ conduit,
             float* __restrict__ out) {
    __shared__ float sq[2][RN + 2 * SPAD];

    const int tid = threadIdx.x;
    const int tx = tid & 15, ty = tid >> 4;
    const int px = tx * 3, py = ty * 3;
    const int ox = blockIdx.x * TS - KF;
    const int oy = blockIdx.y * TS - KF;

    const float* __restrict__ qsrc = g_q[qsel];
    float*       __restrict__ qdst = g_q[qsel ^ 1];

    // zero guard pads (one row above/below region, never written afterwards)
    if (tid < SPAD) {
        sq[0][tid] = 0.0f;
        sq[1][tid] = 0.0f;
        sq[0][SPAD + RN + tid] = 0.0f;
        sq[1][SPAD + RN + tid] = 0.0f;
    }

    const int base = SPAD + py * RW + px;

    float4 w[3][3];
    float  ro[3][3];
    float  q[3][3];
#pragma unroll
    for (int r = 0; r < 3; r++) {
#pragma unroll
        for (int c = 0; c < 3; c++) {
            const int gy = oy + py + r, gx = ox + px + c;
            const bool ok = (gx >= 0) & (gx < COLS) & (gy >= 0) & (gy < ROWS);
            const int g = gy * COLS + gx;
            float4 wv = make_float4(0.0f, 0.0f, 0.0f, 0.0f);
            float rv = 0.0f, qv = 0.0f;
            if (ok) {
                wv = g_w4[g];
                rv = g_runoff[g];
                qv = INIT ? rv : qsrc[g];
            }
            w[r][c] = wv; ro[r][c] = rv; q[r][c] = qv;
            if (!(r == 1 && c == 1)) sq[0][base + r * RW + c] = qv;  // seed borders
        }
    }
    __syncthreads();

#pragma unroll
    for (int it = 0; it < KF; it++) {
        const int cur = it & 1;
        const float* __restrict__ qs = sq[cur];
        float*       __restrict__ qd = sq[cur ^ 1];

        // center cell first: pure-register, overlaps the ring LDS latency
        float n11 = ro[1][1];
        n11 = fmaf(w[1][1].x, q[1][0], n11);
        n11 = fmaf(w[1][1].y, q[1][2], n11);
        n11 = fmaf(w[1][1].z, q[0][1], n11);
        n11 = fmaf(w[1][1].w, q[2][1], n11);

        // 12-ring from neighboring threads (previous iteration values)
        float t0 = qs[base - RW],     t1 = qs[base - RW + 1],     t2 = qs[base - RW + 2];
        float b0 = qs[base + 3 * RW], b1 = qs[base + 3 * RW + 1], b2 = qs[base + 3 * RW + 2];
        float l0 = qs[base - 1],      l1 = qs[base + RW - 1],     l2 = qs[base + 2 * RW - 1];
        float r0 = qs[base + 3],      r1 = qs[base + RW + 3],     r2 = qs[base + 2 * RW + 3];

        float n[3][3];
#pragma unroll
        for (int r = 0; r < 3; r++) {
#pragma unroll
            for (int c = 0; c < 3; c++) {
                if (r == 1 && c == 1) { n[1][1] = n11; continue; }
                const float lf = (c == 0) ? ((r == 0) ? l0 : (r == 1) ? l1 : l2) : q[r][c - 1];
                const float rt = (c == 2) ? ((r == 0) ? r0 : (r == 1) ? r1 : r2) : q[r][c + 1];
                const float up = (r == 0) ? ((c == 0) ? t0 : (c == 1) ? t1 : t2) : q[r - 1][c];
                const float dn = (r == 2) ? ((c == 0) ? b0 : (c == 1) ? b1 : b2) : q[r + 1][c];
                float acc = ro[r][c];
                acc = fmaf(w[r][c].x, lf, acc);
                acc = fmaf(w[r][c].y, rt, acc);
                acc = fmaf(w[r][c].z, up, acc);
                acc = fmaf(w[r][c].w, dn, acc);
                n[r][c] = acc;
            }
        }
#pragma unroll
        for (int r = 0; r < 3; r++)
#pragma unroll
            for (int c = 0; c < 3; c++) q[r][c] = n[r][c];

        if (it != KF - 1) {
            // publish only the 8 border cells of the patch
            qd[base]              = q[0][0];
            qd[base + 1]          = q[0][1];
            qd[base + 2]          = q[0][2];
            qd[base + RW]         = q[1][0];
            qd[base + RW + 2]     = q[1][2];
            qd[base + 2 * RW]     = q[2][0];
            qd[base + 2 * RW + 1] = q[2][1];
            qd[base + 2 * RW + 2] = q[2][2];
            __syncthreads();
        }
    }

    // write central 32x32 from registers
#pragma unroll
    for (int r = 0; r < 3; r++) {
#pragma unroll
        for (int c = 0; c < 3; c++) {
            const int ly = py + r, lx = px + c;
            if (lx >= KF && lx < KF + TS && ly >= KF && ly < KF + TS) {
                const int gy = oy + ly, gx = ox + lx;
                const int g = gy * COLS + gx;
                if (FINAL) {
                    const float cd = conduit[g];
                    const float c125 = cd * sqrtf(sqrtf(cd));   // conduit^1.25
                    const float t = q[r][c] * FLOW_COEFF * c125;
                    const bool core = (gx >= 1) & (gx <= COLS - 2) & (gy >= 1) & (gy <= ROWS - 2);
                    out[g] = core ? (t * t) : 0.0f;
                } else {
                    qdst[g] = q[r][c];
                }
            }
        }
    }
}

extern "C" void kernel_launch(void* const* d_in, const int* in_sizes, int n_in,
                              void* d_out, int out_size) {
    const float* melt    = (const float*)d_in[0];
    const float* bed     = (const float*)d_in[1];
    const float* wp      = (const float*)d_in[2];
    const float* area    = (const float*)d_in[3];
    const float* conduit = (const float*)d_in[4];
    const int*   status  = (const int*)d_in[5];
    float* out = (float*)d_out;

    dim3 pgrid(COLS / PT, ROWS / PT);
    k_prep<<<pgrid, 256>>>(melt, bed, wp, area, status);

    dim3 grid(COLS / TS, ROWS / TS);   // 32 x 32 tiles
    // 4 launches x 8 fused iterations = 32 iterations total
    k_fused<true,  false><<<grid, 256>>>(0, conduit, out);  // runoff -> g_q[1]
    k_fused<false, false><<<grid, 256>>>(1, conduit, out);  // g_q[1] -> g_q[0]
    k_fused<false, false><<<grid, 256>>>(0, conduit, out);  // g_q[0] -> g_q[1]
    k_fused<false, true ><<<grid, 256>>>(1, conduit, out);  // g_q[1] -> out
}